// round 5
// baseline (speedup 1.0000x reference)
#include <cuda_runtime.h>
#include <cuda_fp16.h>
#include <cstdint>
#include <math.h>

// Problem constants
#define NIMG 32
#define LSEQ 196
#define KEEP 98
#define SEQ  99
#define DMODEL 1024
#define NHEAD 16
#define DHEAD 64
#define DMLP 4096
#define NLAYER 6
#define PDIM 768
#define NTOK (NIMG*SEQ)  // 3168
#define NPAT (NIMG*LSEQ) // 6272
#define QKVN (3*DMODEL)  // 3072
#define NSLOT 13

// ======================= scratch (device globals) =======================
__device__ __half g_patches[(size_t)NPAT*PDIM];
__device__ float  g_x0[(size_t)NPAT*DMODEL];
__device__ float  g_x [(size_t)NTOK*DMODEL];
__device__ __half g_qkv[(size_t)NTOK*QKVN];
__device__ __half g_ao[(size_t)NTOK*DMODEL];
__device__ __half g_h1[(size_t)NTOK*DMLP];
__device__ int    g_keep[NIMG*KEEP];
__device__ float  g_sum[(size_t)NSLOT*NTOK];
__device__ float  g_ssq[(size_t)NSLOT*NTOK];
// transposed half weights (K-major, [N,K])
__device__ __half g_pwt[(size_t)DMODEL*PDIM];
__device__ __half g_wqkvt[(size_t)NLAYER*QKVN*DMODEL];
__device__ __half g_wot[(size_t)NLAYER*DMODEL*DMODEL];
__device__ __half g_w1t[(size_t)NLAYER*DMLP*DMODEL];
__device__ __half g_w2t[(size_t)NLAYER*DMODEL*DMLP];
__device__ float  g_bqkv[(size_t)NLAYER*QKVN];

// ======================= helpers =======================
__device__ __forceinline__ uint32_t smem_u32(const void* p) {
    uint32_t a;
    asm("{ .reg .u64 t; cvta.to.shared.u64 t, %1; cvt.u32.u64 %0, t; }" : "=r"(a) : "l"(p));
    return a;
}
__device__ __forceinline__ void cp_async16(uint32_t dst, const void* src, bool ok) {
    asm volatile("cp.async.ca.shared.global [%0], [%1], 16, %2;"
                 :: "r"(dst), "l"(src), "r"(ok ? 16 : 0) : "memory");
}
#define CP_COMMIT() asm volatile("cp.async.commit_group;" ::: "memory")
#define CP_WAIT(n)  asm volatile("cp.async.wait_group %0;" :: "n"(n) : "memory")

__device__ __forceinline__ void ldmx4(uint32_t r[4], uint32_t addr) {
    asm volatile("ldmatrix.sync.aligned.m8n8.x4.shared.b16 {%0,%1,%2,%3}, [%4];"
                 : "=r"(r[0]), "=r"(r[1]), "=r"(r[2]), "=r"(r[3]) : "r"(addr));
}
__device__ __forceinline__ void mma_f16(float c[4], const uint32_t a[4],
                                        uint32_t b0, uint32_t b1) {
    asm volatile(
        "mma.sync.aligned.m16n8k16.row.col.f32.f16.f16.f32 "
        "{%0,%1,%2,%3}, {%4,%5,%6,%7}, {%8,%9}, {%0,%1,%2,%3};\n"
        : "+f"(c[0]), "+f"(c[1]), "+f"(c[2]), "+f"(c[3])
        : "r"(a[0]), "r"(a[1]), "r"(a[2]), "r"(a[3]), "r"(b0), "r"(b1));
}
__device__ __forceinline__ float gelu_f(float x) {
    float x3 = x * x * x;
    return 0.5f * x * (1.0f + tanhf(0.7978845608028654f * (x + 0.044715f * x3)));
}

// ======================= fp16 mma.sync GEMM (+fused LN in, +stats out) ====
#define BM 128
#define BN 128
#define BKH 64
#define A_TILE_B (BM * BKH * 2)      // 16384 bytes
#define STAGE_B (2 * A_TILE_B)       // 32768
#define NSTAGE 3
#define GEMM_SMEM (NSTAGE * STAGE_B) // 98304

__global__ void __launch_bounds__(256, 2)
gemm_h(const void* __restrict__ Ain, const __half* __restrict__ Bt,
       const float* __restrict__ bias, const float* __restrict__ res,
       float* __restrict__ Cf, __half* __restrict__ Ch,
       int M, int N, int K, int act,
       const float* __restrict__ lnS, const float* __restrict__ lnB,
       const float* __restrict__ sumIn, const float* __restrict__ ssqIn,
       float* __restrict__ sumOut, float* __restrict__ ssqOut) {
    extern __shared__ char smem[];
    const bool lnMode = (lnS != nullptr);
    const __half* Ah = (const __half*)Ain;
    const float*  Af = (const float*)Ain;

    int tid = threadIdx.x;
    int wid = tid >> 5, lane = tid & 31;
    int g = lane >> 2, tg = lane & 3;
    int warp_m = wid & 3, warp_n = wid >> 2;  // 4 x 2
    int m0 = blockIdx.y * BM, n0 = blockIdx.x * BN;

    uint32_t sbase = smem_u32(smem);

    float acc[2][8][4];
#pragma unroll
    for (int i = 0; i < 2; i++)
#pragma unroll
        for (int j = 0; j < 8; j++)
#pragma unroll
            for (int l = 0; l < 4; l++) acc[i][j][l] = 0.f;

    int ldr = tid >> 1;
    int ldc0 = (tid & 1) * 4;
    bool aok = (m0 + ldr) < M;
    bool bok = (n0 + ldr) < N;
    int sw = ldr & 7;

    float aMean = 0.f, aRstd = 0.f;
    if (lnMode && aok) {
        float s_ = sumIn[m0 + ldr], q_ = ssqIn[m0 + ldr];
        aMean = s_ * (1.0f / (float)K);
        float var = q_ * (1.0f / (float)K) - aMean * aMean;
        aRstd = rsqrtf(var + 1e-6f);
    }

    auto load_stage = [&](int c) {
        int slot = c % NSTAGE;
        int k0 = c * BKH;
        uint32_t da = sbase + slot * STAGE_B + ldr * 128;
        uint32_t db = da + A_TILE_B;
        const __half* gb = Bt + (size_t)(n0 + ldr) * K + k0 + ldc0 * 8;
#pragma unroll
        for (int q = 0; q < 4; q++) {
            uint32_t off = (uint32_t)(((ldc0 + q) ^ sw) * 16);
            cp_async16(db + off, gb + q * 8, bok);
        }
        if (!lnMode) {
            const __half* ga = Ah + (size_t)(m0 + ldr) * K + k0 + ldc0 * 8;
#pragma unroll
            for (int q = 0; q < 4; q++) {
                uint32_t off = (uint32_t)(((ldc0 + q) ^ sw) * 16);
                cp_async16(da + off, ga + q * 8, aok);
            }
        } else {
            const float* ga = Af + (size_t)(m0 + ldr) * K + k0 + ldc0 * 8;
            const float* sS = lnS + k0 + ldc0 * 8;
            const float* sB = lnB + k0 + ldc0 * 8;
#pragma unroll
            for (int q = 0; q < 4; q++) {
                float4 u0 = aok ? *(const float4*)(ga + q * 8)     : make_float4(0.f,0.f,0.f,0.f);
                float4 u1 = aok ? *(const float4*)(ga + q * 8 + 4) : make_float4(0.f,0.f,0.f,0.f);
                float4 s0 = *(const float4*)(sS + q * 8);
                float4 s1 = *(const float4*)(sS + q * 8 + 4);
                float4 b0 = *(const float4*)(sB + q * 8);
                float4 b1 = *(const float4*)(sB + q * 8 + 4);
                __half2 hh[4];
                hh[0] = __floats2half2_rn((u0.x - aMean) * aRstd * s0.x + b0.x,
                                          (u0.y - aMean) * aRstd * s0.y + b0.y);
                hh[1] = __floats2half2_rn((u0.z - aMean) * aRstd * s0.z + b0.z,
                                          (u0.w - aMean) * aRstd * s0.w + b0.w);
                hh[2] = __floats2half2_rn((u1.x - aMean) * aRstd * s1.x + b1.x,
                                          (u1.y - aMean) * aRstd * s1.y + b1.y);
                hh[3] = __floats2half2_rn((u1.z - aMean) * aRstd * s1.z + b1.z,
                                          (u1.w - aMean) * aRstd * s1.w + b1.w);
                uint32_t off = (uint32_t)(((ldc0 + q) ^ sw) * 16);
                *(uint4*)(smem + slot * STAGE_B + ldr * 128 + off) = *(uint4*)hh;
            }
        }
        CP_COMMIT();
    };

    const int NC = K / BKH;
    load_stage(0);
    load_stage(1);

    int rA = warp_m * 32 + ((lane >> 3) & 1) * 8 + (lane & 7);
    int kAh = (lane >> 4) & 1;
    int rB = warp_n * 64 + ((lane >> 4) & 1) * 8 + (lane & 7);
    int kBh = (lane >> 3) & 1;

    for (int c = 0; c < NC; c++) {
        CP_WAIT(1);
        __syncthreads();
        int slot = c % NSTAGE;
        uint32_t aBase = sbase + slot * STAGE_B;
        uint32_t bBase = aBase + A_TILE_B;

#pragma unroll
        for (int ks = 0; ks < 4; ks++) {
            uint32_t a[2][4];
#pragma unroll
            for (int mt = 0; mt < 2; mt++) {
                int row = rA + mt * 16;
                uint32_t addr = aBase + row * 128 + (uint32_t)(((2 * ks + kAh) ^ (row & 7)) * 16);
                ldmx4(a[mt], addr);
            }
            uint32_t b[4][4];
#pragma unroll
            for (int nt2 = 0; nt2 < 4; nt2++) {
                int row = rB + nt2 * 16;
                uint32_t addr = bBase + row * 128 + (uint32_t)(((2 * ks + kBh) ^ (row & 7)) * 16);
                ldmx4(b[nt2], addr);
            }
#pragma unroll
            for (int mt = 0; mt < 2; mt++)
#pragma unroll
                for (int nt2 = 0; nt2 < 4; nt2++) {
                    mma_f16(acc[mt][2 * nt2 + 0], a[mt], b[nt2][0], b[nt2][1]);
                    mma_f16(acc[mt][2 * nt2 + 1], a[mt], b[nt2][2], b[nt2][3]);
                }
        }
        __syncthreads();
        if (c + 2 < NC) load_stage(c + 2);
        else CP_COMMIT();
    }

    // epilogue (+ optional row stats)
#pragma unroll
    for (int mt = 0; mt < 2; mt++) {
#pragma unroll
        for (int hh = 0; hh < 2; hh++) {
            int row = m0 + warp_m * 32 + mt * 16 + g + hh * 8;
            bool rok = row < M;
            const float* rrow = (rok && res) ? res + (size_t)row * N : nullptr;
            float ps_ = 0.f, qs_ = 0.f;
#pragma unroll
            for (int j = 0; j < 8; j++) {
                if (!rok) continue;
                int col = n0 + warp_n * 64 + (j >> 1) * 16 + (j & 1) * 8 + 2 * tg;
                float v0 = acc[mt][j][hh * 2 + 0] + bias[col];
                float v1 = acc[mt][j][hh * 2 + 1] + bias[col + 1];
                if (act == 1) { v0 = gelu_f(v0); v1 = gelu_f(v1); }
                if (rrow) { v0 += rrow[col]; v1 += rrow[col + 1]; }
                if (Ch) {
                    *(__half2*)(Ch + (size_t)row * N + col) = __floats2half2_rn(v0, v1);
                } else {
                    float2 o; o.x = v0; o.y = v1;
                    *(float2*)(Cf + (size_t)row * N + col) = o;
                }
                ps_ += v0 + v1;
                qs_ += v0 * v0 + v1 * v1;
            }
            if (sumOut) {
                ps_ += __shfl_xor_sync(0xffffffffu, ps_, 1);
                qs_ += __shfl_xor_sync(0xffffffffu, qs_, 1);
                ps_ += __shfl_xor_sync(0xffffffffu, ps_, 2);
                qs_ += __shfl_xor_sync(0xffffffffu, qs_, 2);
                if (rok && tg == 0) {
                    atomicAdd(&sumOut[row], ps_);
                    atomicAdd(&ssqOut[row], qs_);
                }
            }
        }
    }
}

// ======================= unified weight prep =======================
#define TPW  768                     // patch_w tiles
#define TSQL 1024                    // 1024x1024 tiles per layer
#define TW1L 4096                    // 1024x4096 tiles per layer
#define Z_PW   0
#define Z_WQ   (Z_PW + TPW)
#define Z_WK   (Z_WQ + NLAYER*TSQL)
#define Z_WV   (Z_WK + NLAYER*TSQL)
#define Z_WO   (Z_WV + NLAYER*TSQL)
#define Z_W1   (Z_WO + NLAYER*TSQL)
#define Z_W2   (Z_W1 + NLAYER*TW1L)
#define Z_BIAS (Z_W2 + NLAYER*TW1L)
#define Z_TOT  (Z_BIAS + 72)

__global__ void wprep_kernel(const float* __restrict__ pw,
                             const float* __restrict__ wq, const float* __restrict__ wk,
                             const float* __restrict__ wv, const float* __restrict__ wo,
                             const float* __restrict__ w1, const float* __restrict__ w2,
                             const float* __restrict__ bq, const float* __restrict__ bk,
                             const float* __restrict__ bv,
                             __half* __restrict__ pwt, __half* __restrict__ wqkvt,
                             __half* __restrict__ wot, __half* __restrict__ w1t,
                             __half* __restrict__ w2t, float* __restrict__ bqkv) {
    __shared__ float t[32][33];
    int z = blockIdx.x;
    const size_t DD = (size_t)DMODEL * DMODEL;
    const size_t DM = (size_t)DMODEL * DMLP;

    auto tr = [&](const float* ip, __half* op, int R, int C, int tx, int ty) {
        int c0 = tx * 32, r0 = ty * 32;
#pragma unroll
        for (int i = threadIdx.y; i < 32; i += 8)
            t[i][threadIdx.x] = ip[(size_t)(r0 + i) * C + c0 + threadIdx.x];
        __syncthreads();
#pragma unroll
        for (int i = threadIdx.y; i < 32; i += 8)
            op[(size_t)(c0 + i) * R + r0 + threadIdx.x] = __float2half_rn(t[threadIdx.x][i]);
    };

    if (z < Z_WQ) {
        int r = z - Z_PW;
        tr(pw, pwt, PDIM, DMODEL, r % 32, r / 32);
    } else if (z < Z_WK) {
        int r = z - Z_WQ; int l = r / TSQL; r %= TSQL;
        tr(wq + l * DD, wqkvt + l * 3 * DD, DMODEL, DMODEL, r % 32, r / 32);
    } else if (z < Z_WV) {
        int r = z - Z_WK; int l = r / TSQL; r %= TSQL;
        tr(wk + l * DD, wqkvt + l * 3 * DD + DD, DMODEL, DMODEL, r % 32, r / 32);
    } else if (z < Z_WO) {
        int r = z - Z_WV; int l = r / TSQL; r %= TSQL;
        tr(wv + l * DD, wqkvt + l * 3 * DD + 2 * DD, DMODEL, DMODEL, r % 32, r / 32);
    } else if (z < Z_W1) {
        int r = z - Z_WO; int l = r / TSQL; r %= TSQL;
        tr(wo + l * DD, wot + l * DD, DMODEL, DMODEL, r % 32, r / 32);
    } else if (z < Z_W2) {
        int r = z - Z_W1; int l = r / TW1L; r %= TW1L;
        tr(w1 + l * DM, w1t + l * DM, DMODEL, DMLP, r % 128, r / 128);
    } else if (z < Z_BIAS) {
        int r = z - Z_W2; int l = r / TW1L; r %= TW1L;
        tr(w2 + l * DM, w2t + l * DM, DMLP, DMODEL, r % 32, r / 32);
    } else {
        int idx = (z - Z_BIAS) * 256 + threadIdx.y * 32 + threadIdx.x;
        if (idx < NLAYER * QKVN) {
            int l = idx / QKVN, j = idx % QKVN;
            float v;
            if (j < DMODEL) v = bq[l * DMODEL + j];
            else if (j < 2 * DMODEL) v = bk[l * DMODEL + j - DMODEL];
            else v = bv[l * DMODEL + j - 2 * DMODEL];
            bqkv[idx] = v;
        }
    }
}

// ======================= patchify (half out) =======================
__global__ void patchify_kernel(const float* __restrict__ imgs, __half* __restrict__ out) {
    int idx = blockIdx.x * blockDim.x + threadIdx.x;
    if (idx >= NPAT * PDIM) return;
    int j = idx % PDIM;
    int l = (idx / PDIM) % LSEQ;
    int n = idx / (PDIM * LSEQ);
    int c  = j % 3;
    int px = (j / 3) % 16;
    int py = j / 48;
    int pw = l % 14;
    int ph = l / 14;
    out[idx] = __float2half_rn(imgs[(((size_t)n * 224 + ph * 16 + py) * 224 + pw * 16 + px) * 3 + c]);
}

// ======================= ranking / mask =======================
__global__ void rank_kernel(const float* __restrict__ noise, int* __restrict__ keep,
                            float* __restrict__ mask_out) {
    int n = blockIdx.x;
    __shared__ float ns[LSEQ];
    int i = threadIdx.x;
    if (i < LSEQ) ns[i] = noise[n * LSEQ + i];
    __syncthreads();
    if (i < LSEQ) {
        float my = ns[i];
        int r = 0;
        for (int j = 0; j < LSEQ; j++) {
            float vj = ns[j];
            r += (vj < my) || (vj == my && j < i);
        }
        if (r < KEEP) keep[n * KEEP + r] = i;
        mask_out[n * LSEQ + i] = (r < KEEP) ? 0.0f : 1.0f;
    }
}

// ======================= zero stats =======================
__global__ void zero_kernel(float* __restrict__ p) {
    int i = blockIdx.x * 256 + threadIdx.x;
    if (i < NSLOT * NTOK) p[i] = 0.f;
}

// ======================= gather + cls + pos (+stats slot0) =======================
__global__ void gather_kernel(const float* __restrict__ x0, const float* __restrict__ pos,
                              const float* __restrict__ cls, const int* __restrict__ keep,
                              float* __restrict__ x, float* __restrict__ sum0,
                              float* __restrict__ ssq0) {
    int b = blockIdx.x;
    int n = b / SEQ, s = b % SEQ;
    float* xo = x + (size_t)b * DMODEL;
    int tid = threadIdx.x;
    float ls = 0.f, lq = 0.f;
    if (s == 0) {
        for (int d = tid; d < DMODEL; d += 256) {
            float v = cls[d]; xo[d] = v; ls += v; lq += v * v;
        }
    } else {
        int id = keep[n * KEEP + s - 1];
        const float* src = x0 + ((size_t)n * LSEQ + id) * DMODEL;
        const float* pp  = pos + (size_t)id * DMODEL;
        for (int d = tid; d < DMODEL; d += 256) {
            float v = src[d] + pp[d]; xo[d] = v; ls += v; lq += v * v;
        }
    }
    __shared__ float rs[256], rq[256];
    rs[tid] = ls; rq[tid] = lq; __syncthreads();
    for (int o = 128; o > 0; o >>= 1) {
        if (tid < o) { rs[tid] += rs[tid + o]; rq[tid] += rq[tid + o]; }
        __syncthreads();
    }
    if (tid == 0) { sum0[b] = rs[0]; ssq0[b] = rq[0]; }
}

// ======================= final layer norm =======================
__global__ void ln_kernel(const float* __restrict__ x, const float* __restrict__ s,
                          const float* __restrict__ b, float* __restrict__ y) {
    int t = blockIdx.x;
    __shared__ float row[DMODEL];
    __shared__ float red[256];
    const float* xr = x + (size_t)t * DMODEL;
    int tid = threadIdx.x;
    float lsum = 0.f;
    for (int i = tid; i < DMODEL; i += 256) { float v = xr[i]; row[i] = v; lsum += v; }
    red[tid] = lsum; __syncthreads();
    for (int o = 128; o > 0; o >>= 1) { if (tid < o) red[tid] += red[tid + o]; __syncthreads(); }
    float m = red[0] * (1.0f / DMODEL);
    __syncthreads();
    float lvar = 0.f;
    for (int i = tid; i < DMODEL; i += 256) { float d = row[i] - m; lvar += d * d; }
    red[tid] = lvar; __syncthreads();
    for (int o = 128; o > 0; o >>= 1) { if (tid < o) red[tid] += red[tid + o]; __syncthreads(); }
    float rstd = rsqrtf(red[0] * (1.0f / DMODEL) + 1e-6f);
    float* yr = y + (size_t)t * DMODEL;
    for (int i = tid; i < DMODEL; i += 256)
        yr[i] = (row[i] - m) * rstd * s[i] + b[i];
}

// ======================= attention (half I/O, fp32 math, smem K+V) ==========
__global__ void attn_kernel(const __half* __restrict__ qkv, __half* __restrict__ o) {
    int nh = blockIdx.x;
    int n = nh / NHEAD, h = nh % NHEAD;
    __shared__ float Ks[SEQ][DHEAD + 1];
    __shared__ __half2 Vs[SEQ][DHEAD / 2];
    __shared__ float ps[4][SEQ];
    __shared__ float qs[4][DHEAD];
    int tid = threadIdx.x;
    int w = tid >> 5, lane = tid & 31;

    const __half* qb = qkv + (size_t)n * SEQ * QKVN + h * DHEAD;
    const __half* kb = qb + DMODEL;
    const __half* vb = qb + 2 * DMODEL;
    __half* ob = o + (size_t)n * SEQ * DMODEL + h * DHEAD;

    for (int idx = tid; idx < SEQ * DHEAD; idx += 128) {
        int j = idx / DHEAD, d = idx % DHEAD;
        Ks[j][d] = __half2float(kb[(size_t)j * QKVN + d]);
    }
    for (int idx = tid; idx < SEQ * (DHEAD / 2); idx += 128) {
        int j = idx >> 5, d2 = idx & 31;
        Vs[j][d2] = *(const __half2*)(vb + (size_t)j * QKVN + 2 * d2);
    }
    __syncthreads();

    for (int si = w; si < SEQ; si += 4) {
        qs[w][lane]      = __half2float(qb[(size_t)si * QKVN + lane]);
        qs[w][lane + 32] = __half2float(qb[(size_t)si * QKVN + lane + 32]);
        __syncwarp();
        float sc[4];
#pragma unroll
        for (int m = 0; m < 4; m++) {
            int j = lane + m * 32;
            float a = 0.f;
            if (j < SEQ) {
#pragma unroll 8
                for (int d = 0; d < DHEAD; d++) a += qs[w][d] * Ks[j][d];
                sc[m] = a * 0.125f;
            } else sc[m] = -1e30f;
        }
        float mx = fmaxf(fmaxf(sc[0], sc[1]), fmaxf(sc[2], sc[3]));
#pragma unroll
        for (int off = 16; off > 0; off >>= 1) mx = fmaxf(mx, __shfl_xor_sync(0xffffffffu, mx, off));
        float sum = 0.f;
#pragma unroll
        for (int m = 0; m < 4; m++) {
            int j = lane + m * 32;
            float e = (j < SEQ) ? __expf(sc[m] - mx) : 0.f;
            sc[m] = e; sum += e;
        }
#pragma unroll
        for (int off = 16; off > 0; off >>= 1) sum += __shfl_xor_sync(0xffffffffu, sum, off);
        float inv = 1.0f / sum;
#pragma unroll
        for (int m = 0; m < 4; m++) {
            int j = lane + m * 32;
            if (j < SEQ) ps[w][j] = sc[m] * inv;
        }
        __syncwarp();
        float a0 = 0.f, a1 = 0.f;
        for (int j = 0; j < SEQ; j++) {
            float pv = ps[w][j];
            float2 vf = __half22float2(Vs[j][lane]);
            a0 += pv * vf.x;
            a1 += pv * vf.y;
        }
        *(__half2*)(ob + (size_t)si * DMODEL + 2 * lane) = __floats2half2_rn(a0, a1);
        __syncwarp();
    }
}

// ======================= launch =======================
extern "C" void kernel_launch(void* const* d_in, const int* in_sizes, int n_in,
                              void* d_out, int out_size) {
    const float* imgs    = (const float*)d_in[0];
    const float* noise   = (const float*)d_in[1];
    const float* patch_w = (const float*)d_in[2];
    const float* patch_b = (const float*)d_in[3];
    const float* pos_emb = (const float*)d_in[4];
    const float* cls_tok = (const float*)d_in[5];
    const float* ln1_s   = (const float*)d_in[6];
    const float* ln1_b   = (const float*)d_in[7];
    const float* wq      = (const float*)d_in[8];
    const float* bq      = (const float*)d_in[9];
    const float* wk      = (const float*)d_in[10];
    const float* bk      = (const float*)d_in[11];
    const float* wv      = (const float*)d_in[12];
    const float* bv      = (const float*)d_in[13];
    const float* wo      = (const float*)d_in[14];
    const float* bo      = (const float*)d_in[15];
    const float* ln2_s   = (const float*)d_in[16];
    const float* ln2_b   = (const float*)d_in[17];
    const float* w1      = (const float*)d_in[18];
    const float* b1      = (const float*)d_in[19];
    const float* w2      = (const float*)d_in[20];
    const float* b2      = (const float*)d_in[21];
    const float* lnf_s   = (const float*)d_in[22];
    const float* lnf_b   = (const float*)d_in[23];

    float* out = (float*)d_out;
    float* out_mask = out + (size_t)NTOK * DMODEL;

    __half *patches, *qkv, *ao, *h1, *pwt, *wqkvt, *wot, *w1t, *w2t;
    float *x0, *x, *bqkv, *gsum, *gssq;
    int* keep;
    cudaGetSymbolAddress((void**)&patches, g_patches);
    cudaGetSymbolAddress((void**)&x0, g_x0);
    cudaGetSymbolAddress((void**)&x,  g_x);
    cudaGetSymbolAddress((void**)&qkv, g_qkv);
    cudaGetSymbolAddress((void**)&ao, g_ao);
    cudaGetSymbolAddress((void**)&h1, g_h1);
    cudaGetSymbolAddress((void**)&keep, g_keep);
    cudaGetSymbolAddress((void**)&pwt, g_pwt);
    cudaGetSymbolAddress((void**)&wqkvt, g_wqkvt);
    cudaGetSymbolAddress((void**)&wot, g_wot);
    cudaGetSymbolAddress((void**)&w1t, g_w1t);
    cudaGetSymbolAddress((void**)&w2t, g_w2t);
    cudaGetSymbolAddress((void**)&bqkv, g_bqkv);
    cudaGetSymbolAddress((void**)&gsum, g_sum);
    cudaGetSymbolAddress((void**)&gssq, g_ssq);

    cudaFuncSetAttribute(gemm_h, cudaFuncAttributeMaxDynamicSharedMemorySize, GEMM_SMEM);

    // 1: patchify, 2: rank, 3-4: zero stats, 5: weight prep
    patchify_kernel<<<(NPAT * PDIM + 255) / 256, 256>>>(imgs, patches);
    rank_kernel<<<NIMG, 224>>>(noise, keep, out_mask);
    zero_kernel<<<(NSLOT * NTOK + 255) / 256, 256>>>(gsum);
    zero_kernel<<<(NSLOT * NTOK + 255) / 256, 256>>>(gssq);
    wprep_kernel<<<Z_TOT, dim3(32, 8)>>>(patch_w, wq, wk, wv, wo, w1, w2, bq, bk, bv,
                                         pwt, wqkvt, wot, w1t, w2t, bqkv);

    // 6: patch embed GEMM (profiled by ncu -s 5 -c 1)
    {
        dim3 grid(DMODEL / BN, NPAT / BM);
        gemm_h<<<grid, 256, GEMM_SMEM>>>(patches, pwt, patch_b, nullptr, x0, nullptr,
                                         NPAT, DMODEL, PDIM, 0,
                                         nullptr, nullptr, nullptr, nullptr, nullptr, nullptr);
    }
    // 7: gather (+stats slot 0)
    gather_kernel<<<NTOK, 256>>>(x0, pos_emb, cls_tok, keep, x, gsum, gssq);

    int gy = (NTOK + BM - 1) / BM;
    dim3 gQKV(QKVN / BN, gy);
    dim3 gD(DMODEL / BN, gy);
    dim3 gM(DMLP / BN, gy);

    for (int i = 0; i < NLAYER; i++) {
        const __half* wqkv_i = wqkvt + (size_t)i * 3 * DMODEL * DMODEL;
        const __half* wo_i = wot + (size_t)i * DMODEL * DMODEL;
        const __half* w1_i = w1t + (size_t)i * DMODEL * DMLP;
        const __half* w2_i = w2t + (size_t)i * DMLP * DMODEL;
        float* s0 = gsum + (size_t)(2 * i) * NTOK;      // ln1 stats (in)
        float* q0 = gssq + (size_t)(2 * i) * NTOK;
        float* s1 = gsum + (size_t)(2 * i + 1) * NTOK;  // ln2 stats
        float* q1 = gssq + (size_t)(2 * i + 1) * NTOK;
        float* s2 = gsum + (size_t)(2 * i + 2) * NTOK;  // next ln1 stats
        float* q2 = gssq + (size_t)(2 * i + 2) * NTOK;

        // QKV: A = LN1(x) fused
        gemm_h<<<gQKV, 256, GEMM_SMEM>>>(x, wqkv_i, bqkv + (size_t)i * QKVN, nullptr,
                                         nullptr, qkv, NTOK, QKVN, DMODEL, 0,
                                         ln1_s + i * DMODEL, ln1_b + i * DMODEL,
                                         s0, q0, nullptr, nullptr);
        attn_kernel<<<NIMG * NHEAD, 128>>>(qkv, ao);
        // O proj: out x (+res) + ln2 stats
        gemm_h<<<gD, 256, GEMM_SMEM>>>(ao, wo_i, bo + i * DMODEL, x, x, nullptr,
                                       NTOK, DMODEL, DMODEL, 0,
                                       nullptr, nullptr, nullptr, nullptr, s1, q1);
        // MLP1: A = LN2(x) fused, gelu, half out
        gemm_h<<<gM, 256, GEMM_SMEM>>>(x, w1_i, b1 + i * DMLP, nullptr,
                                       nullptr, h1, NTOK, DMLP, DMODEL, 1,
                                       ln2_s + i * DMODEL, ln2_b + i * DMODEL,
                                       s1, q1, nullptr, nullptr);
        // MLP2: out x (+res) + next ln1 stats
        gemm_h<<<gD, 256, GEMM_SMEM>>>(h1, w2_i, b2 + i * DMODEL, x, x, nullptr,
                                       NTOK, DMODEL, DMLP, 0,
                                       nullptr, nullptr, nullptr, nullptr, s2, q2);
    }
    ln_kernel<<<NTOK, 256>>>(x, lnf_s, lnf_b, out);
}

// round 7
// speedup vs baseline: 1.6530x; 1.6530x over previous
#include <cuda_runtime.h>
#include <cuda_fp16.h>
#include <cstdint>
#include <math.h>

// Problem constants
#define NIMG 32
#define LSEQ 196
#define KEEP 98
#define SEQ  99
#define DMODEL 1024
#define NHEAD 16
#define DHEAD 64
#define DMLP 4096
#define NLAYER 6
#define PDIM 768
#define NTOK (NIMG*SEQ)  // 3168
#define NPAT (NIMG*LSEQ) // 6272
#define QKVN (3*DMODEL)  // 3072

// ======================= scratch (device globals) =======================
__device__ __half g_patches[(size_t)NPAT*PDIM];
__device__ float  g_x0[(size_t)NPAT*DMODEL];
__device__ float  g_x [(size_t)NTOK*DMODEL];
__device__ __half g_y [(size_t)NTOK*DMODEL];
__device__ __half g_qkv[(size_t)NTOK*QKVN];
__device__ __half g_ao[(size_t)NTOK*DMODEL];
__device__ __half g_h1[(size_t)NTOK*DMLP];
__device__ int    g_keep[NIMG*KEEP];
// transposed half weights (K-major, [N,K])
__device__ __half g_pwt[(size_t)DMODEL*PDIM];
__device__ __half g_wqkvt[(size_t)NLAYER*QKVN*DMODEL];
__device__ __half g_wot[(size_t)NLAYER*DMODEL*DMODEL];
__device__ __half g_w1t[(size_t)NLAYER*DMLP*DMODEL];
__device__ __half g_w2t[(size_t)NLAYER*DMODEL*DMLP];
__device__ float  g_bqkv[(size_t)NLAYER*QKVN];

// ======================= helpers =======================
__device__ __forceinline__ uint32_t smem_u32(const void* p) {
    uint32_t a;
    asm("{ .reg .u64 t; cvta.to.shared.u64 t, %1; cvt.u32.u64 %0, t; }" : "=r"(a) : "l"(p));
    return a;
}
__device__ __forceinline__ void cp_async16(uint32_t dst, const void* src, bool ok) {
    asm volatile("cp.async.ca.shared.global [%0], [%1], 16, %2;"
                 :: "r"(dst), "l"(src), "r"(ok ? 16 : 0) : "memory");
}
#define CP_COMMIT() asm volatile("cp.async.commit_group;" ::: "memory")
#define CP_WAIT(n)  asm volatile("cp.async.wait_group %0;" :: "n"(n) : "memory")

__device__ __forceinline__ void ldmx4(uint32_t r[4], uint32_t addr) {
    asm volatile("ldmatrix.sync.aligned.m8n8.x4.shared.b16 {%0,%1,%2,%3}, [%4];"
                 : "=r"(r[0]), "=r"(r[1]), "=r"(r[2]), "=r"(r[3]) : "r"(addr));
}
__device__ __forceinline__ void mma_f16(float c[4], const uint32_t a[4],
                                        uint32_t b0, uint32_t b1) {
    asm volatile(
        "mma.sync.aligned.m16n8k16.row.col.f32.f16.f16.f32 "
        "{%0,%1,%2,%3}, {%4,%5,%6,%7}, {%8,%9}, {%0,%1,%2,%3};\n"
        : "+f"(c[0]), "+f"(c[1]), "+f"(c[2]), "+f"(c[3])
        : "r"(a[0]), "r"(a[1]), "r"(a[2]), "r"(a[3]), "r"(b0), "r"(b1));
}
__device__ __forceinline__ float gelu_f(float x) {
    float x3 = x * x * x;
    return 0.5f * x * (1.0f + tanhf(0.7978845608028654f * (x + 0.044715f * x3)));
}

// ======================= templated fp16 mma.sync GEMM =======================
// WM x WN warp grid (WM*WN = 8). CTA tile: (WM*32) x 128. NT2 = 128/(WN*16).
#define BKH 64
#define NSTAGE 3

template <int WM, int WN, int NT2>
__global__ void __launch_bounds__(256, 2)
gemm_h(const __half* __restrict__ A, const __half* __restrict__ Bt,
       const float* __restrict__ bias, const float* __restrict__ res,
       float* __restrict__ Cf, __half* __restrict__ Ch,
       int M, int N, int K, int act) {
    constexpr int BM_ = WM * 32;
    constexpr int A_TILE = BM_ * 128;        // bytes
    constexpr int STAGE = A_TILE + 16384;    // + B tile (128 rows x 128B)
    constexpr int TOT_ROWS = BM_ + 128;

    extern __shared__ char smem[];
    int tid = threadIdx.x;
    int wid = tid >> 5, lane = tid & 31;
    int g = lane >> 2, tg = lane & 3;
    int warp_m = wid % WM, warp_n = wid / WM;
    int m0 = blockIdx.y * BM_, n0 = blockIdx.x * 128;

    uint32_t sbase = smem_u32(smem);

    float acc[2][2 * NT2][4];
#pragma unroll
    for (int i = 0; i < 2; i++)
#pragma unroll
        for (int j = 0; j < 2 * NT2; j++)
#pragma unroll
            for (int l = 0; l < 4; l++) acc[i][j][l] = 0.f;

    auto load_stage = [&](int c) {
        int slot = c % NSTAGE;
        int k0 = c * BKH;
        uint32_t base = sbase + slot * STAGE;
#pragma unroll
        for (int u = tid; u < TOT_ROWS * 8; u += 256) {
            int row = u >> 3, q = u & 7;
            uint32_t off = (uint32_t)((q ^ (row & 7)) * 16);
            if (row < BM_) {
                bool ok = (m0 + row) < M;
                cp_async16(base + row * 128 + off,
                           A + (size_t)(m0 + row) * K + k0 + q * 8, ok);
            } else {
                int r2 = row - BM_;
                bool ok = (n0 + r2) < N;
                cp_async16(base + A_TILE + r2 * 128 + off,
                           Bt + (size_t)(n0 + r2) * K + k0 + q * 8, ok);
            }
        }
        CP_COMMIT();
    };

    const int NC = K / BKH;
    load_stage(0);
    load_stage(1);

    int rA = warp_m * 32 + ((lane >> 3) & 1) * 8 + (lane & 7);
    int kAh = (lane >> 4) & 1;
    int rB = warp_n * (NT2 * 16) + ((lane >> 4) & 1) * 8 + (lane & 7);
    int kBh = (lane >> 3) & 1;

    for (int c = 0; c < NC; c++) {
        CP_WAIT(1);
        __syncthreads();
        int slot = c % NSTAGE;
        uint32_t aBase = sbase + slot * STAGE;
        uint32_t bBase = aBase + A_TILE;

#pragma unroll
        for (int ks = 0; ks < 4; ks++) {
            uint32_t a[2][4];
#pragma unroll
            for (int mt = 0; mt < 2; mt++) {
                int row = rA + mt * 16;
                uint32_t addr = aBase + row * 128 + (uint32_t)(((2 * ks + kAh) ^ (row & 7)) * 16);
                ldmx4(a[mt], addr);
            }
            uint32_t b[NT2][4];
#pragma unroll
            for (int nt2 = 0; nt2 < NT2; nt2++) {
                int row = rB + nt2 * 16;
                uint32_t addr = bBase + row * 128 + (uint32_t)(((2 * ks + kBh) ^ (row & 7)) * 16);
                ldmx4(b[nt2], addr);
            }
#pragma unroll
            for (int mt = 0; mt < 2; mt++)
#pragma unroll
                for (int nt2 = 0; nt2 < NT2; nt2++) {
                    mma_f16(acc[mt][2 * nt2 + 0], a[mt], b[nt2][0], b[nt2][1]);
                    mma_f16(acc[mt][2 * nt2 + 1], a[mt], b[nt2][2], b[nt2][3]);
                }
        }
        __syncthreads();
        if (c + 2 < NC) load_stage(c + 2);
        else CP_COMMIT();
    }

    // epilogue
#pragma unroll
    for (int mt = 0; mt < 2; mt++) {
#pragma unroll
        for (int hh = 0; hh < 2; hh++) {
            int row = m0 + warp_m * 32 + mt * 16 + g + hh * 8;
            if (row >= M) continue;
            const float* rrow = res ? res + (size_t)row * N : nullptr;
#pragma unroll
            for (int j = 0; j < 2 * NT2; j++) {
                int col = n0 + warp_n * (NT2 * 16) + (j >> 1) * 16 + (j & 1) * 8 + 2 * tg;
                float v0 = acc[mt][j][hh * 2 + 0] + bias[col];
                float v1 = acc[mt][j][hh * 2 + 1] + bias[col + 1];
                if (act == 1) { v0 = gelu_f(v0); v1 = gelu_f(v1); }
                if (rrow) { v0 += rrow[col]; v1 += rrow[col + 1]; }
                if (Ch) {
                    *(__half2*)(Ch + (size_t)row * N + col) = __floats2half2_rn(v0, v1);
                } else {
                    float2 o; o.x = v0; o.y = v1;
                    *(float2*)(Cf + (size_t)row * N + col) = o;
                }
            }
        }
    }
}

#define SMEM_A (NSTAGE * (128 * 128 + 16384))  // 98304
#define SMEM_B (NSTAGE * (64 * 128 + 16384))   // 73728

// ======================= unified weight prep =======================
#define TPW  768
#define TSQL 1024
#define TW1L 4096
#define Z_PW   0
#define Z_WQ   (Z_PW + TPW)
#define Z_WK   (Z_WQ + NLAYER*TSQL)
#define Z_WV   (Z_WK + NLAYER*TSQL)
#define Z_WO   (Z_WV + NLAYER*TSQL)
#define Z_W1   (Z_WO + NLAYER*TSQL)
#define Z_W2   (Z_W1 + NLAYER*TW1L)
#define Z_BIAS (Z_W2 + NLAYER*TW1L)
#define Z_TOT  (Z_BIAS + 72)

__global__ void wprep_kernel(const float* __restrict__ pw,
                             const float* __restrict__ wq, const float* __restrict__ wk,
                             const float* __restrict__ wv, const float* __restrict__ wo,
                             const float* __restrict__ w1, const float* __restrict__ w2,
                             const float* __restrict__ bq, const float* __restrict__ bk,
                             const float* __restrict__ bv,
                             __half* __restrict__ pwt, __half* __restrict__ wqkvt,
                             __half* __restrict__ wot, __half* __restrict__ w1t,
                             __half* __restrict__ w2t, float* __restrict__ bqkv) {
    __shared__ float t[32][33];
    int z = blockIdx.x;
    const size_t DD = (size_t)DMODEL * DMODEL;
    const size_t DM = (size_t)DMODEL * DMLP;

    auto tr = [&](const float* ip, __half* op, int R, int C, int tx, int ty) {
        int c0 = tx * 32, r0 = ty * 32;
#pragma unroll
        for (int i = threadIdx.y; i < 32; i += 8)
            t[i][threadIdx.x] = ip[(size_t)(r0 + i) * C + c0 + threadIdx.x];
        __syncthreads();
#pragma unroll
        for (int i = threadIdx.y; i < 32; i += 8)
            op[(size_t)(c0 + i) * R + r0 + threadIdx.x] = __float2half_rn(t[threadIdx.x][i]);
    };

    if (z < Z_WQ) {
        int r = z - Z_PW;
        tr(pw, pwt, PDIM, DMODEL, r % 32, r / 32);
    } else if (z < Z_WK) {
        int r = z - Z_WQ; int l = r / TSQL; r %= TSQL;
        tr(wq + l * DD, wqkvt + l * 3 * DD, DMODEL, DMODEL, r % 32, r / 32);
    } else if (z < Z_WV) {
        int r = z - Z_WK; int l = r / TSQL; r %= TSQL;
        tr(wk + l * DD, wqkvt + l * 3 * DD + DD, DMODEL, DMODEL, r % 32, r / 32);
    } else if (z < Z_WO) {
        int r = z - Z_WV; int l = r / TSQL; r %= TSQL;
        tr(wv + l * DD, wqkvt + l * 3 * DD + 2 * DD, DMODEL, DMODEL, r % 32, r / 32);
    } else if (z < Z_W1) {
        int r = z - Z_WO; int l = r / TSQL; r %= TSQL;
        tr(wo + l * DD, wot + l * DD, DMODEL, DMODEL, r % 32, r / 32);
    } else if (z < Z_W2) {
        int r = z - Z_W1; int l = r / TW1L; r %= TW1L;
        tr(w1 + l * DM, w1t + l * DM, DMODEL, DMLP, r % 128, r / 128);
    } else if (z < Z_BIAS) {
        int r = z - Z_W2; int l = r / TW1L; r %= TW1L;
        tr(w2 + l * DM, w2t + l * DM, DMLP, DMODEL, r % 32, r / 32);
    } else {
        int idx = (z - Z_BIAS) * 256 + threadIdx.y * 32 + threadIdx.x;
        if (idx < NLAYER * QKVN) {
            int l = idx / QKVN, j = idx % QKVN;
            float v;
            if (j < DMODEL) v = bq[l * DMODEL + j];
            else if (j < 2 * DMODEL) v = bk[l * DMODEL + j - DMODEL];
            else v = bv[l * DMODEL + j - 2 * DMODEL];
            bqkv[idx] = v;
        }
    }
}

// ======================= patchify (half out) =======================
__global__ void patchify_kernel(const float* __restrict__ imgs, __half* __restrict__ out) {
    int idx = blockIdx.x * blockDim.x + threadIdx.x;
    if (idx >= NPAT * PDIM) return;
    int j = idx % PDIM;
    int l = (idx / PDIM) % LSEQ;
    int n = idx / (PDIM * LSEQ);
    int c  = j % 3;
    int px = (j / 3) % 16;
    int py = j / 48;
    int pw = l % 14;
    int ph = l / 14;
    out[idx] = __float2half_rn(imgs[(((size_t)n * 224 + ph * 16 + py) * 224 + pw * 16 + px) * 3 + c]);
}

// ======================= ranking / mask =======================
__global__ void rank_kernel(const float* __restrict__ noise, int* __restrict__ keep,
                            float* __restrict__ mask_out) {
    int n = blockIdx.x;
    __shared__ float ns[LSEQ];
    int i = threadIdx.x;
    if (i < LSEQ) ns[i] = noise[n * LSEQ + i];
    __syncthreads();
    if (i < LSEQ) {
        float my = ns[i];
        int r = 0;
        for (int j = 0; j < LSEQ; j++) {
            float vj = ns[j];
            r += (vj < my) || (vj == my && j < i);
        }
        if (r < KEEP) keep[n * KEEP + r] = i;
        mask_out[n * LSEQ + i] = (r < KEEP) ? 0.0f : 1.0f;
    }
}

// ======================= gather + cls + pos =======================
__global__ void gather_kernel(const float* __restrict__ x0, const float* __restrict__ pos,
                              const float* __restrict__ cls, const int* __restrict__ keep,
                              float* __restrict__ x) {
    int b = blockIdx.x;
    int n = b / SEQ, s = b % SEQ;
    float* xo = x + (size_t)b * DMODEL;
    if (s == 0) {
        for (int d = threadIdx.x; d < DMODEL; d += blockDim.x) xo[d] = cls[d];
    } else {
        int id = keep[n * KEEP + s - 1];
        const float* src = x0 + ((size_t)n * LSEQ + id) * DMODEL;
        const float* pp  = pos + (size_t)id * DMODEL;
        for (int d = threadIdx.x; d < DMODEL; d += blockDim.x) xo[d] = src[d] + pp[d];
    }
}

// ======================= layer norm (fp32 in; half or fp32 out) =======================
__global__ void ln_kernel(const float* __restrict__ x, const float* __restrict__ s,
                          const float* __restrict__ b, float* __restrict__ yf,
                          __half* __restrict__ yh) {
    int t = blockIdx.x;
    __shared__ float row[DMODEL];
    __shared__ float red[256];
    const float* xr = x + (size_t)t * DMODEL;
    int tid = threadIdx.x;
    float lsum = 0.f;
    for (int i = tid; i < DMODEL; i += 256) { float v = xr[i]; row[i] = v; lsum += v; }
    red[tid] = lsum; __syncthreads();
    for (int o = 128; o > 0; o >>= 1) { if (tid < o) red[tid] += red[tid + o]; __syncthreads(); }
    float m = red[0] * (1.0f / DMODEL);
    __syncthreads();
    float lvar = 0.f;
    for (int i = tid; i < DMODEL; i += 256) { float d = row[i] - m; lvar += d * d; }
    red[tid] = lvar; __syncthreads();
    for (int o = 128; o > 0; o >>= 1) { if (tid < o) red[tid] += red[tid + o]; __syncthreads(); }
    float rstd = rsqrtf(red[0] * (1.0f / DMODEL) + 1e-6f);
    if (yh) {
        __half* yr = yh + (size_t)t * DMODEL;
        for (int i = tid; i < DMODEL; i += 256)
            yr[i] = __float2half_rn((row[i] - m) * rstd * s[i] + b[i]);
    } else {
        float* yr = yf + (size_t)t * DMODEL;
        for (int i = tid; i < DMODEL; i += 256)
            yr[i] = (row[i] - m) * rstd * s[i] + b[i];
    }
}

// ======================= attention (half I/O, fp32 math, smem K+V) ==========
__global__ void attn_kernel(const __half* __restrict__ qkv, __half* __restrict__ o) {
    int nh = blockIdx.x;
    int n = nh / NHEAD, h = nh % NHEAD;
    __shared__ float Ks[SEQ][DHEAD + 1];
    __shared__ __half2 Vs[SEQ][DHEAD / 2];
    __shared__ float ps[4][SEQ];
    __shared__ float qs[4][DHEAD];
    int tid = threadIdx.x;
    int w = tid >> 5, lane = tid & 31;

    const __half* qb = qkv + (size_t)n * SEQ * QKVN + h * DHEAD;
    const __half* kb = qb + DMODEL;
    const __half* vb = qb + 2 * DMODEL;
    __half* ob = o + (size_t)n * SEQ * DMODEL + h * DHEAD;

    for (int idx = tid; idx < SEQ * DHEAD; idx += 128) {
        int j = idx / DHEAD, d = idx % DHEAD;
        Ks[j][d] = __half2float(kb[(size_t)j * QKVN + d]);
    }
    for (int idx = tid; idx < SEQ * (DHEAD / 2); idx += 128) {
        int j = idx >> 5, d2 = idx & 31;
        Vs[j][d2] = *(const __half2*)(vb + (size_t)j * QKVN + 2 * d2);
    }
    __syncthreads();

    for (int si = w; si < SEQ; si += 4) {
        qs[w][lane]      = __half2float(qb[(size_t)si * QKVN + lane]);
        qs[w][lane + 32] = __half2float(qb[(size_t)si * QKVN + lane + 32]);
        __syncwarp();
        float sc[4];
#pragma unroll
        for (int m = 0; m < 4; m++) {
            int j = lane + m * 32;
            float a = 0.f;
            if (j < SEQ) {
#pragma unroll 8
                for (int d = 0; d < DHEAD; d++) a += qs[w][d] * Ks[j][d];
                sc[m] = a * 0.125f;
            } else sc[m] = -1e30f;
        }
        float mx = fmaxf(fmaxf(sc[0], sc[1]), fmaxf(sc[2], sc[3]));
#pragma unroll
        for (int off = 16; off > 0; off >>= 1) mx = fmaxf(mx, __shfl_xor_sync(0xffffffffu, mx, off));
        float sum = 0.f;
#pragma unroll
        for (int m = 0; m < 4; m++) {
            int j = lane + m * 32;
            float e = (j < SEQ) ? __expf(sc[m] - mx) : 0.f;
            sc[m] = e; sum += e;
        }
#pragma unroll
        for (int off = 16; off > 0; off >>= 1) sum += __shfl_xor_sync(0xffffffffu, sum, off);
        float inv = 1.0f / sum;
#pragma unroll
        for (int m = 0; m < 4; m++) {
            int j = lane + m * 32;
            if (j < SEQ) ps[w][j] = sc[m] * inv;
        }
        __syncwarp();
        float a0 = 0.f, a1 = 0.f;
        for (int j = 0; j < SEQ; j++) {
            float pv = ps[w][j];
            float2 vf = __half22float2(Vs[j][lane]);
            a0 += pv * vf.x;
            a1 += pv * vf.y;
        }
        *(__half2*)(ob + (size_t)si * DMODEL + 2 * lane) = __floats2half2_rn(a0, a1);
        __syncwarp();
    }
}

// ======================= launch =======================
extern "C" void kernel_launch(void* const* d_in, const int* in_sizes, int n_in,
                              void* d_out, int out_size) {
    const float* imgs    = (const float*)d_in[0];
    const float* noise   = (const float*)d_in[1];
    const float* patch_w = (const float*)d_in[2];
    const float* patch_b = (const float*)d_in[3];
    const float* pos_emb = (const float*)d_in[4];
    const float* cls_tok = (const float*)d_in[5];
    const float* ln1_s   = (const float*)d_in[6];
    const float* ln1_b   = (const float*)d_in[7];
    const float* wq      = (const float*)d_in[8];
    const float* bq      = (const float*)d_in[9];
    const float* wk      = (const float*)d_in[10];
    const float* bk      = (const float*)d_in[11];
    const float* wv      = (const float*)d_in[12];
    const float* bv      = (const float*)d_in[13];
    const float* wo      = (const float*)d_in[14];
    const float* bo      = (const float*)d_in[15];
    const float* ln2_s   = (const float*)d_in[16];
    const float* ln2_b   = (const float*)d_in[17];
    const float* w1      = (const float*)d_in[18];
    const float* b1      = (const float*)d_in[19];
    const float* w2      = (const float*)d_in[20];
    const float* b2      = (const float*)d_in[21];
    const float* lnf_s   = (const float*)d_in[22];
    const float* lnf_b   = (const float*)d_in[23];

    float* out = (float*)d_out;
    float* out_mask = out + (size_t)NTOK * DMODEL;

    __half *patches, *y, *qkv, *ao, *h1, *pwt, *wqkvt, *wot, *w1t, *w2t;
    float *x0, *x, *bqkv;
    int* keep;
    cudaGetSymbolAddress((void**)&patches, g_patches);
    cudaGetSymbolAddress((void**)&x0, g_x0);
    cudaGetSymbolAddress((void**)&x,  g_x);
    cudaGetSymbolAddress((void**)&y,  g_y);
    cudaGetSymbolAddress((void**)&qkv, g_qkv);
    cudaGetSymbolAddress((void**)&ao, g_ao);
    cudaGetSymbolAddress((void**)&h1, g_h1);
    cudaGetSymbolAddress((void**)&keep, g_keep);
    cudaGetSymbolAddress((void**)&pwt, g_pwt);
    cudaGetSymbolAddress((void**)&wqkvt, g_wqkvt);
    cudaGetSymbolAddress((void**)&wot, g_wot);
    cudaGetSymbolAddress((void**)&w1t, g_w1t);
    cudaGetSymbolAddress((void**)&w2t, g_w2t);
    cudaGetSymbolAddress((void**)&bqkv, g_bqkv);

    cudaFuncSetAttribute(gemm_h<4, 2, 4>, cudaFuncAttributeMaxDynamicSharedMemorySize, SMEM_A);
    cudaFuncSetAttribute(gemm_h<2, 4, 2>, cudaFuncAttributeMaxDynamicSharedMemorySize, SMEM_B);

    patchify_kernel<<<(NPAT * PDIM + 255) / 256, 256>>>(imgs, patches);
    rank_kernel<<<NIMG, 224>>>(noise, keep, out_mask);
    wprep_kernel<<<Z_TOT, dim3(32, 8)>>>(patch_w, wq, wk, wv, wo, w1, w2, bq, bk, bv,
                                         pwt, wqkvt, wot, w1t, w2t, bqkv);

    // patch embed: M=6272, N=1024
    {
        dim3 grid(DMODEL / 128, NPAT / 128);
        gemm_h<4, 2, 4><<<grid, 256, SMEM_A>>>(patches, pwt, patch_b, nullptr, x0, nullptr,
                                               NPAT, DMODEL, PDIM, 0);
    }
    gather_kernel<<<NTOK, 256>>>(x0, pos_emb, cls_tok, keep, x);

    dim3 gQKV(QKVN / 128, (NTOK + 127) / 128);    // 24 x 25
    dim3 gD64(DMODEL / 128, (NTOK + 63) / 64);    // 8 x 50
    dim3 gM(DMLP / 128, (NTOK + 127) / 128);      // 32 x 25

    for (int i = 0; i < NLAYER; i++) {
        const __half* wqkv_i = wqkvt + (size_t)i * 3 * DMODEL * DMODEL;
        const __half* wo_i = wot + (size_t)i * DMODEL * DMODEL;
        const __half* w1_i = w1t + (size_t)i * DMODEL * DMLP;
        const __half* w2_i = w2t + (size_t)i * DMLP * DMODEL;

        ln_kernel<<<NTOK, 256>>>(x, ln1_s + i * DMODEL, ln1_b + i * DMODEL, nullptr, y);
        gemm_h<4, 2, 4><<<gQKV, 256, SMEM_A>>>(y, wqkv_i, bqkv + (size_t)i * QKVN, nullptr,
                                               nullptr, qkv, NTOK, QKVN, DMODEL, 0);
        attn_kernel<<<NIMG * NHEAD, 128>>>(qkv, ao);
        gemm_h<2, 4, 2><<<gD64, 256, SMEM_B>>>(ao, wo_i, bo + i * DMODEL, x, x, nullptr,
                                               NTOK, DMODEL, DMODEL, 0);
        ln_kernel<<<NTOK, 256>>>(x, ln2_s + i * DMODEL, ln2_b + i * DMODEL, nullptr, y);
        gemm_h<4, 2, 4><<<gM, 256, SMEM_A>>>(y, w1_i, b1 + i * DMLP, nullptr,
                                             nullptr, h1, NTOK, DMLP, DMODEL, 1);
        gemm_h<2, 4, 2><<<gD64, 256, SMEM_B>>>(h1, w2_i, b2 + i * DMODEL, x, x, nullptr,
                                               NTOK, DMODEL, DMLP, 0);
    }
    ln_kernel<<<NTOK, 256>>>(x, lnf_s, lnf_b, out, nullptr);
}